// round 14
// baseline (speedup 1.0000x reference)
#include <cuda_runtime.h>
#include <cuda_fp16.h>
#include <cstdint>
#include <cstddef>

// B=8, N=1024, C=1024, H=16, D=64, scale = 0.125
#define BB 8
#define NN 1024
#define CC 1024
#define HH 16
#define DD 64
#define SCALE 0.125f
#define FROWS 16

__device__ __half g_xh[(size_t)BB * NN * CC];
__device__ __half g_qkvh[(size_t)BB * NN * 3 * CC];    // (B,N,3,H,D)
__device__ __half g_ctxh[(size_t)BB * NN * CC];
__device__ __half g_wqkvT[(size_t)3 * CC * CC];        // [n][k]
__device__ __half g_wprojT[(size_t)CC * CC];           // [n][k]
__device__ __half g_vt[(size_t)BB * HH * DD * NN];     // [bh][d][m]

__device__ __forceinline__ unsigned pack_h2(float a, float b) {
    __half2 h = __floats2half2_rn(a, b);
    return *reinterpret_cast<unsigned*>(&h);
}

__device__ __forceinline__ void mma_f16(float c[4],
    unsigned a0, unsigned a1, unsigned a2, unsigned a3,
    unsigned b0, unsigned b1)
{
    asm volatile(
        "mma.sync.aligned.m16n8k16.row.col.f32.f16.f16.f32 "
        "{%0,%1,%2,%3}, {%4,%5,%6,%7}, {%8,%9}, {%0,%1,%2,%3};\n"
        : "+f"(c[0]), "+f"(c[1]), "+f"(c[2]), "+f"(c[3])
        : "r"(a0), "r"(a1), "r"(a2), "r"(a3), "r"(b0), "r"(b1));
}

__device__ __forceinline__ void ldmx4(unsigned& r0, unsigned& r1,
                                      unsigned& r2, unsigned& r3,
                                      const void* p)
{
    unsigned addr = (unsigned)__cvta_generic_to_shared(p);
    asm volatile(
        "ldmatrix.sync.aligned.m8n8.x4.shared.b16 {%0,%1,%2,%3}, [%4];\n"
        : "=r"(r0), "=r"(r1), "=r"(r2), "=r"(r3) : "r"(addr));
}

__device__ __forceinline__ void cp16(void* smem, const void* gmem) {
    unsigned s = (unsigned)__cvta_generic_to_shared(smem);
    asm volatile("cp.async.cg.shared.global [%0], [%1], 16;\n"
                 :: "r"(s), "l"(gmem) : "memory");
}

// ---------------------------------------------------------------------------
__global__ void cvt_f32_h(const float* __restrict__ in,
                          __half* __restrict__ out, int n8)
{
    int i = blockIdx.x * blockDim.x + threadIdx.x;
    if (i >= n8) return;
    const float4* p = reinterpret_cast<const float4*>(in) + (size_t)i * 2;
    float4 v0 = p[0], v1 = p[1];
    uint4 u;
    u.x = pack_h2(v0.x, v0.y);
    u.y = pack_h2(v0.z, v0.w);
    u.z = pack_h2(v1.x, v1.y);
    u.w = pack_h2(v1.z, v1.w);
    reinterpret_cast<uint4*>(out)[i] = u;
}

__global__ void transpose_w_h(const float* __restrict__ W,
                              __half* __restrict__ WT, int K, int N)
{
    __shared__ float tile[32][33];
    const int k0 = blockIdx.x * 32, n0 = blockIdx.y * 32;
    for (int i = threadIdx.y; i < 32; i += 8)
        tile[i][threadIdx.x] = W[(size_t)(k0 + i) * N + n0 + threadIdx.x];
    __syncthreads();
    for (int i = threadIdx.y; i < 32; i += 8)
        WT[(size_t)(n0 + i) * K + k0 + threadIdx.x] =
            __float2half_rn(tile[threadIdx.x][i]);
}

__global__ __launch_bounds__(256) void transpose_v_h(
    const __half* __restrict__ qkvh, __half* __restrict__ vt)
{
    __shared__ __half tile[128][72];
    const int bh = blockIdx.y;
    const int b = bh >> 4, h = bh & 15;
    const int m0 = blockIdx.x * 128;
    const __half* vb = qkvh + (size_t)b * NN * 3 * CC + 2 * CC + h * DD;

#pragma unroll
    for (int it = 0; it < 4; it++) {
        const int idx = threadIdx.x + 256 * it;
        const int m = idx >> 3, c8 = idx & 7;
        uint4 v = *reinterpret_cast<const uint4*>(
            vb + (size_t)(m0 + m) * 3 * CC + c8 * 8);
        *reinterpret_cast<uint4*>(&tile[m][c8 * 8]) = v;
    }
    __syncthreads();
    __half* ob = vt + (size_t)bh * DD * NN + m0;
#pragma unroll
    for (int it = 0; it < 4; it++) {
        const int idx = threadIdx.x + 256 * it;
        const int d = idx >> 4, mc = idx & 15;
        __half hbuf[8];
#pragma unroll
        for (int j = 0; j < 8; j++) hbuf[j] = tile[mc * 8 + j][d];
        *reinterpret_cast<uint4*>(ob + (size_t)d * NN + mc * 8) =
            *reinterpret_cast<uint4*>(hbuf);
    }
}

// ---------------------------------------------------------------------------
// fp16 TC GEMM + bias (unchanged from R12, tail-safe cp.async ring).
// ---------------------------------------------------------------------------
__global__ __launch_bounds__(256, 2) void gemm_h3(
    const __half* __restrict__ Ah, const __half* __restrict__ BT,
    const float* __restrict__ bias, void* __restrict__ Cout,
    int M, int N, int K, int out_half)
{
    extern __shared__ __align__(16) char dsm[];
    char* sA = dsm;
    char* sB = dsm + 3 * 10240;

    const int tid  = threadIdx.x;
    const int brow = blockIdx.y * 128;
    const int bcol = blockIdx.x * 128;
    const int w = tid >> 5, l = tid & 31;
    const int wr = w >> 2, wc = w & 3;
    const int g = l >> 2, t = l & 3;

    const int arow = l & 15;
    const int acol = (l >> 4) * 8;
    const int brow8 = ((l >> 4) * 8) + (l & 7);
    const int bcol8 = ((l >> 3) & 1) * 8;

    auto cp_stage = [&](int kc, int st) {
        const int k0 = kc << 5;
#pragma unroll
        for (int j = 0; j < 2; j++) {
            const int i = tid + 256 * j;
            const int r = i >> 2, c = i & 3;
            cp16(sA + st * 10240 + r * 80 + c * 16,
                 Ah + (size_t)(brow + r) * K + k0 + c * 8);
        }
#pragma unroll
        for (int j = 0; j < 2; j++) {
            const int i = tid + 256 * j;
            const int r = i >> 2, c = i & 3;
            cp16(sB + st * 10240 + r * 80 + c * 16,
                 BT + (size_t)(bcol + r) * K + k0 + c * 8);
        }
        asm volatile("cp.async.commit_group;\n" ::: "memory");
    };

    float acc[4][4][4];
#pragma unroll
    for (int i = 0; i < 4; i++)
#pragma unroll
        for (int j = 0; j < 4; j++)
#pragma unroll
            for (int r = 0; r < 4; r++) acc[i][j][r] = 0.0f;

    const int nIter = K >> 5;
    cp_stage(0, 0);
    cp_stage(1, 1);
    for (int it = 0; it < nIter; it++) {
        if (it + 1 < nIter)
            asm volatile("cp.async.wait_group 1;\n" ::: "memory");
        else
            asm volatile("cp.async.wait_group 0;\n" ::: "memory");
        __syncthreads();
        const int st = it % 3;
        const __half* pA = reinterpret_cast<const __half*>(sA + st * 10240);
        const __half* pB = reinterpret_cast<const __half*>(sB + st * 10240);
#pragma unroll
        for (int ss = 0; ss < 2; ss++) {
            const int kk = ss * 16;
            unsigned a[4][4], b[4][2];
#pragma unroll
            for (int i = 0; i < 4; i++)
                ldmx4(a[i][0], a[i][1], a[i][2], a[i][3],
                      pA + (wr * 64 + i * 16 + arow) * 40 + kk + acol);
#pragma unroll
            for (int jp = 0; jp < 2; jp++)
                ldmx4(b[jp * 2][0], b[jp * 2][1],
                      b[jp * 2 + 1][0], b[jp * 2 + 1][1],
                      pB + (wc * 32 + jp * 16 + brow8) * 40 + kk + bcol8);
#pragma unroll
            for (int i = 0; i < 4; i++)
#pragma unroll
                for (int j = 0; j < 4; j++)
                    mma_f16(acc[i][j], a[i][0], a[i][1], a[i][2], a[i][3],
                            b[j][0], b[j][1]);
        }
        if (it + 2 < nIter) cp_stage(it + 2, (it + 2) % 3);
    }

    if (out_half) {
        __half* C = reinterpret_cast<__half*>(Cout);
#pragma unroll
        for (int j = 0; j < 4; j++) {
            const int col = bcol + wc * 32 + j * 8 + 2 * t;
            const float b0 = bias[col], b1 = bias[col + 1];
#pragma unroll
            for (int i = 0; i < 4; i++) {
                const int r0 = brow + wr * 64 + i * 16;
                *reinterpret_cast<unsigned*>(&C[(size_t)(r0 + g) * N + col]) =
                    pack_h2(acc[i][j][0] + b0, acc[i][j][1] + b1);
                *reinterpret_cast<unsigned*>(&C[(size_t)(r0 + g + 8) * N + col]) =
                    pack_h2(acc[i][j][2] + b0, acc[i][j][3] + b1);
            }
        }
    } else {
        float* C = reinterpret_cast<float*>(Cout);
#pragma unroll
        for (int j = 0; j < 4; j++) {
            const int col = bcol + wc * 32 + j * 8 + 2 * t;
            const float b0 = bias[col], b1 = bias[col + 1];
#pragma unroll
            for (int i = 0; i < 4; i++) {
                const int r0 = brow + wr * 64 + i * 16;
                float2 o0 = {acc[i][j][0] + b0, acc[i][j][1] + b1};
                float2 o1 = {acc[i][j][2] + b0, acc[i][j][3] + b1};
                *reinterpret_cast<float2*>(&C[(size_t)(r0 + g) * N + col]) = o0;
                *reinterpret_cast<float2*>(&C[(size_t)(r0 + g + 8) * N + col]) = o1;
            }
        }
    }
}

// ---------------------------------------------------------------------------
// Fully fused attention, 256-thread CTA (16 rows x 1024 keys), 2 CTAs/SM.
// 8 warps, warp wc owns keys (c*128 + wc*16) per chunk c.
// Dyn smem (phases overlay): Qs[16][72] | Ks[3][128][72] = 57600 B;
// PV Vs[2][64][136]=34816; red [4][8][32] float4 = 16384.
// ---------------------------------------------------------------------------
__global__ __launch_bounds__(256, 2) void attn_fused_h(
    const __half* __restrict__ qkvh, const __half* __restrict__ vt,
    float* __restrict__ attn, __half* __restrict__ ctxh)
{
    extern __shared__ __align__(16) char dyn[];
    __half* Qs = reinterpret_cast<__half*>(dyn);            // [16][72]
    __half* Ks = Qs + 16 * 72;                              // [3][128][72]
    __half* Vs = reinterpret_cast<__half*>(dyn);            // [2][64][136]
    float4* redO = reinterpret_cast<float4*>(dyn);          // [4][8][32]
    __shared__ float redM[16 * 9];
    __shared__ float redS[16 * 9];

    const int bh = blockIdx.y;
    const int b = bh >> 4, h = bh & 15;
    const int n0 = blockIdx.x * FROWS;

    const int tid = threadIdx.x;
    const int wc = tid >> 5, l = tid & 31;
    const int g = l >> 2, t = l & 3;

    const int arow = l & 15;
    const int acol = (l >> 4) * 8;
    const int brow8 = ((l >> 4) * 8) + (l & 7);
    const int bcol8 = ((l >> 3) & 1) * 8;

    const __half* qb = qkvh + (size_t)b * NN * 3 * CC + h * DD;
    const __half* kb = qb + CC;
    const __half* vb = vt + (size_t)bh * DD * NN;

    // ---------------- Phase 1: QK^T ----------------
    auto cp_k = [&](int c, int st) {
        const int m0 = c * 128;
#pragma unroll
        for (int j = 0; j < 4; j++) {
            const int idx = tid * 4 + j;
            const int m = idx >> 3, c8 = idx & 7;
            cp16(Ks + (st * 128 + m) * 72 + c8 * 8,
                 kb + (size_t)(m0 + m) * 3 * CC + c8 * 8);
        }
        asm volatile("cp.async.commit_group;\n" ::: "memory");
    };

    cp_k(0, 0);
    cp_k(1, 1);

    if (tid < 128) {
        const int row = tid >> 3, c8 = tid & 7;
        *reinterpret_cast<uint4*>(Qs + row * 72 + c8 * 8) =
            *reinterpret_cast<const uint4*>(qb + (size_t)(n0 + row) * 3 * CC + c8 * 8);
    }
    __syncthreads();

    unsigned qa[4][4];
#pragma unroll
    for (int ss = 0; ss < 4; ss++)
        ldmx4(qa[ss][0], qa[ss][1], qa[ss][2], qa[ss][3],
              Qs + arow * 72 + ss * 16 + acol);

    float acc[8][2][4];
#pragma unroll
    for (int c = 0; c < 8; c++)
#pragma unroll
        for (int jn = 0; jn < 2; jn++)
#pragma unroll
            for (int r = 0; r < 4; r++) acc[c][jn][r] = 0.0f;

    const int row0 = g;
    const int row1 = g + 8;

#pragma unroll
    for (int c = 0; c < 8; c++) {
        if (c + 1 < 8)
            asm volatile("cp.async.wait_group 1;\n" ::: "memory");
        else
            asm volatile("cp.async.wait_group 0;\n" ::: "memory");
        __syncthreads();
        const int st = c % 3;
#pragma unroll
        for (int ss = 0; ss < 4; ss++) {
            const int kk = ss * 16;
            unsigned kb0, kb1, kb2, kb3;
            ldmx4(kb0, kb1, kb2, kb3,
                  Ks + (st * 128 + wc * 16 + brow8) * 72 + kk + bcol8);
            mma_f16(acc[c][0], qa[ss][0], qa[ss][1], qa[ss][2], qa[ss][3], kb0, kb1);
            mma_f16(acc[c][1], qa[ss][0], qa[ss][1], qa[ss][2], qa[ss][3], kb2, kb3);
        }
        if (c + 2 < 8) cp_k(c + 2, (c + 2) % 3);
    }

    // ---------------- Phase 2: softmax ----------------
#pragma unroll
    for (int c = 0; c < 8; c++)
#pragma unroll
        for (int jn = 0; jn < 2; jn++)
#pragma unroll
            for (int r = 0; r < 4; r++) acc[c][jn][r] *= SCALE;

    float mx0 = -3.402823466e+38f, mx1 = -3.402823466e+38f;
#pragma unroll
    for (int c = 0; c < 8; c++)
#pragma unroll
        for (int jn = 0; jn < 2; jn++) {
            mx0 = fmaxf(mx0, fmaxf(acc[c][jn][0], acc[c][jn][1]));
            mx1 = fmaxf(mx1, fmaxf(acc[c][jn][2], acc[c][jn][3]));
        }
#pragma unroll
    for (int o = 1; o <= 2; o <<= 1) {
        mx0 = fmaxf(mx0, __shfl_xor_sync(0xffffffffu, mx0, o));
        mx1 = fmaxf(mx1, __shfl_xor_sync(0xffffffffu, mx1, o));
    }
    if (t == 0) {
        redM[row0 * 9 + wc] = mx0;
        redM[row1 * 9 + wc] = mx1;
    }
    __syncthreads();
    mx0 = redM[row0 * 9];
    mx1 = redM[row1 * 9];
#pragma unroll
    for (int k = 1; k < 8; k++) {
        mx0 = fmaxf(mx0, redM[row0 * 9 + k]);
        mx1 = fmaxf(mx1, redM[row1 * 9 + k]);
    }

    float s0 = 0.0f, s1 = 0.0f;
#pragma unroll
    for (int c = 0; c < 8; c++)
#pragma unroll
        for (int jn = 0; jn < 2; jn++) {
            acc[c][jn][0] = __expf(acc[c][jn][0] - mx0);
            acc[c][jn][1] = __expf(acc[c][jn][1] - mx0);
            acc[c][jn][2] = __expf(acc[c][jn][2] - mx1);
            acc[c][jn][3] = __expf(acc[c][jn][3] - mx1);
            s0 += acc[c][jn][0] + acc[c][jn][1];
            s1 += acc[c][jn][2] + acc[c][jn][3];
        }
#pragma unroll
    for (int o = 1; o <= 2; o <<= 1) {
        s0 += __shfl_xor_sync(0xffffffffu, s0, o);
        s1 += __shfl_xor_sync(0xffffffffu, s1, o);
    }
    if (t == 0) {
        redS[row0 * 9 + wc] = s0;
        redS[row1 * 9 + wc] = s1;
    }
    __syncthreads();
    s0 = redS[row0 * 9];
    s1 = redS[row1 * 9];
#pragma unroll
    for (int k = 1; k < 8; k++) {
        s0 += redS[row0 * 9 + k];
        s1 += redS[row1 * 9 + k];
    }
    const float inv0 = 1.0f / s0;
    const float inv1 = 1.0f / s1;

#pragma unroll
    for (int c = 0; c < 8; c++)
#pragma unroll
        for (int jn = 0; jn < 2; jn++) {
            acc[c][jn][0] *= inv0;
            acc[c][jn][1] *= inv0;
            acc[c][jn][2] *= inv1;
            acc[c][jn][3] *= inv1;
        }

    // ---------------- Phase 3: write attn ----------------
    {
        float* arow0 = attn + ((size_t)bh * NN + n0 + row0) * NN;
        float* arow1 = attn + ((size_t)bh * NN + n0 + row1) * NN;
#pragma unroll
        for (int c = 0; c < 8; c++)
#pragma unroll
            for (int jn = 0; jn < 2; jn++) {
                const int col = c * 128 + wc * 16 + jn * 8 + 2 * t;
                float2 o0 = {acc[c][jn][0], acc[c][jn][1]};
                float2 o1 = {acc[c][jn][2], acc[c][jn][3]};
                *reinterpret_cast<float2*>(&arow0[col]) = o0;
                *reinterpret_cast<float2*>(&arow1[col]) = o1;
            }
    }

    // ---------------- Phase 4: PV (P frags from registers) ----------------
    float oacc[8][4];
#pragma unroll
    for (int j = 0; j < 8; j++)
#pragma unroll
        for (int r = 0; r < 4; r++) oacc[j][r] = 0.0f;

    uint4 vpre[4];
    auto ldg_v = [&](int c) {
#pragma unroll
        for (int j = 0; j < 4; j++) {
            const int idx = tid + 256 * j;
            const int d = idx >> 4, k8 = idx & 15;
            vpre[j] = *reinterpret_cast<const uint4*>(
                vb + (size_t)d * NN + c * 128 + k8 * 8);
        }
    };
    auto sts_v = [&](int st) {
#pragma unroll
        for (int j = 0; j < 4; j++) {
            const int idx = tid + 256 * j;
            const int d = idx >> 4, k8 = idx & 15;
            *reinterpret_cast<uint4*>(Vs + (st * 64 + d) * 136 + k8 * 8) = vpre[j];
        }
    };

    __syncthreads();    // QK smem reads done; Vs overlays Qs/Ks
    ldg_v(0);
    sts_v(0);
    __syncthreads();
#pragma unroll
    for (int c = 0; c < 8; c++) {
        if (c + 1 < 8) ldg_v(c + 1);
        const int st = c & 1;
        const unsigned pa0 = pack_h2(acc[c][0][0], acc[c][0][1]);
        const unsigned pa1 = pack_h2(acc[c][0][2], acc[c][0][3]);
        const unsigned pa2 = pack_h2(acc[c][1][0], acc[c][1][1]);
        const unsigned pa3 = pack_h2(acc[c][1][2], acc[c][1][3]);
        unsigned bf[8][2];
#pragma unroll
        for (int jp = 0; jp < 4; jp++)
            ldmx4(bf[jp * 2][0], bf[jp * 2][1],
                  bf[jp * 2 + 1][0], bf[jp * 2 + 1][1],
                  Vs + (st * 64 + jp * 16 + brow8) * 136 + wc * 16 + bcol8);
#pragma unroll
        for (int j = 0; j < 8; j++)
            mma_f16(oacc[j], pa0, pa1, pa2, pa3, bf[j][0], bf[j][1]);
        if (c + 1 < 8) { sts_v((c + 1) & 1); __syncthreads(); }
    }

    // ---------------- Phase 5: cross-warp reduction (8 warps) ----------------
    __syncthreads();    // PV reads done; redO overlays Vs
    if (wc >= 4) {
        const int area = wc - 4;
#pragma unroll
        for (int j = 0; j < 8; j++) {
            float4 v = {oacc[j][0], oacc[j][1], oacc[j][2], oacc[j][3]};
            redO[(area * 8 + j) * 32 + l] = v;
        }
    }
    __syncthreads();
    if (wc < 4) {
#pragma unroll
        for (int j = 0; j < 8; j++) {
            float4 v = redO[(wc * 8 + j) * 32 + l];
            oacc[j][0] += v.x; oacc[j][1] += v.y;
            oacc[j][2] += v.z; oacc[j][3] += v.w;
        }
    }
    __syncthreads();
    if (wc >= 2 && wc < 4) {
        const int area = wc - 2;
#pragma unroll
        for (int j = 0; j < 8; j++) {
            float4 v = {oacc[j][0], oacc[j][1], oacc[j][2], oacc[j][3]};
            redO[(area * 8 + j) * 32 + l] = v;
        }
    }
    __syncthreads();
    if (wc < 2) {
#pragma unroll
        for (int j = 0; j < 8; j++) {
            float4 v = redO[(wc * 8 + j) * 32 + l];
            oacc[j][0] += v.x; oacc[j][1] += v.y;
            oacc[j][2] += v.z; oacc[j][3] += v.w;
        }
    }
    __syncthreads();
    if (wc == 1) {
#pragma unroll
        for (int j = 0; j < 8; j++) {
            float4 v = {oacc[j][0], oacc[j][1], oacc[j][2], oacc[j][3]};
            redO[j * 32 + l] = v;
        }
    }
    __syncthreads();
    if (wc == 0) {
#pragma unroll
        for (int j = 0; j < 8; j++) {
            float4 v = redO[j * 32 + l];
            oacc[j][0] += v.x; oacc[j][1] += v.y;
            oacc[j][2] += v.z; oacc[j][3] += v.w;
        }
        const int r0 = n0 + g;
#pragma unroll
        for (int j = 0; j < 8; j++) {
            const int col = h * DD + j * 8 + 2 * t;
            *reinterpret_cast<unsigned*>(
                &ctxh[((size_t)b * NN + r0) * CC + col]) =
                pack_h2(oacc[j][0], oacc[j][1]);
            *reinterpret_cast<unsigned*>(
                &ctxh[((size_t)b * NN + r0 + 8) * CC + col]) =
                pack_h2(oacc[j][2], oacc[j][3]);
        }
    }
}

// ---------------------------------------------------------------------------
extern "C" void kernel_launch(void* const* d_in, const int* in_sizes, int n_in,
                              void* d_out, int out_size)
{
    (void)in_sizes; (void)n_in; (void)out_size;
    const float* x      = (const float*)d_in[0];
    const float* w_qkv  = (const float*)d_in[1];
    const float* b_qkv  = (const float*)d_in[2];
    const float* w_proj = (const float*)d_in[3];
    const float* b_proj = (const float*)d_in[4];

    float* out  = (float*)d_out;
    float* attn = out + (size_t)BB * NN * CC;

    __half *xh, *qkvh, *ctxh, *wqkvT, *wprojT, *vt;
    cudaGetSymbolAddress((void**)&xh, g_xh);
    cudaGetSymbolAddress((void**)&qkvh, g_qkvh);
    cudaGetSymbolAddress((void**)&ctxh, g_ctxh);
    cudaGetSymbolAddress((void**)&wqkvT, g_wqkvT);
    cudaGetSymbolAddress((void**)&wprojT, g_wprojT);
    cudaGetSymbolAddress((void**)&vt, g_vt);

    const int g_smem = 6 * 10240;                     // 61440
    const int a_smem = (16 * 72 + 3 * 128 * 72) * 2;  // 57600
    cudaFuncSetAttribute(gemm_h3,
        cudaFuncAttributeMaxDynamicSharedMemorySize, g_smem);
    cudaFuncSetAttribute(attn_fused_h,
        cudaFuncAttributeMaxDynamicSharedMemorySize, a_smem);

    // 0) One-time conversions
    const int nx8 = BB * NN * CC / 8;
    cvt_f32_h<<<(nx8 + 255) / 256, 256>>>(x, xh, nx8);
    transpose_w_h<<<dim3(CC / 32, 3 * CC / 32), dim3(32, 8)>>>(
        w_qkv, wqkvT, CC, 3 * CC);
    transpose_w_h<<<dim3(CC / 32, CC / 32), dim3(32, 8)>>>(
        w_proj, wprojT, CC, CC);

    // 1) QKV projection (fp16 out)
    gemm_h3<<<dim3(3 * CC / 128, BB * NN / 128), 256, g_smem>>>(
        xh, wqkvT, b_qkv, qkvh, BB * NN, 3 * CC, CC, 1);

    // 1b) V transpose -> [bh][d][m]
    transpose_v_h<<<dim3(NN / 128, BB * HH), 256>>>(qkvh, vt);

    // 2) Fully fused attention (16 rows/CTA, 2 CTAs/SM)
    attn_fused_h<<<dim3(NN / FROWS, BB * HH), 256, a_smem>>>(
        qkvh, vt, attn, ctxh);

    // 3) Output projection (fp32 out)
    gemm_h3<<<dim3(CC / 128, BB * NN / 128), 256, g_smem>>>(
        ctxh, wprojT, b_proj, out, BB * NN, CC, CC, 0);
}

// round 15
// speedup vs baseline: 1.0884x; 1.0884x over previous
#include <cuda_runtime.h>
#include <cuda_fp16.h>
#include <cstdint>
#include <cstddef>

// B=8, N=1024, C=1024, H=16, D=64, scale = 0.125
#define BB 8
#define NN 1024
#define CC 1024
#define HH 16
#define DD 64
#define SCALE 0.125f
#define FROWS 32

__device__ __half g_xh[(size_t)BB * NN * CC];
__device__ __half g_qkvh[(size_t)BB * NN * 3 * CC];    // (B,N,3,H,D)
__device__ __half g_ctxh[(size_t)BB * NN * CC];
__device__ __half g_wqkvT[(size_t)3 * CC * CC];        // [n][k]
__device__ __half g_wprojT[(size_t)CC * CC];           // [n][k]
__device__ __half g_vt[(size_t)BB * HH * DD * NN];     // [bh][d][m]

__device__ __forceinline__ unsigned pack_h2(float a, float b) {
    __half2 h = __floats2half2_rn(a, b);
    return *reinterpret_cast<unsigned*>(&h);
}

__device__ __forceinline__ void mma_f16(float c[4],
    unsigned a0, unsigned a1, unsigned a2, unsigned a3,
    unsigned b0, unsigned b1)
{
    asm volatile(
        "mma.sync.aligned.m16n8k16.row.col.f32.f16.f16.f32 "
        "{%0,%1,%2,%3}, {%4,%5,%6,%7}, {%8,%9}, {%0,%1,%2,%3};\n"
        : "+f"(c[0]), "+f"(c[1]), "+f"(c[2]), "+f"(c[3])
        : "r"(a0), "r"(a1), "r"(a2), "r"(a3), "r"(b0), "r"(b1));
}

__device__ __forceinline__ void ldmx4(unsigned& r0, unsigned& r1,
                                      unsigned& r2, unsigned& r3,
                                      const void* p)
{
    unsigned addr = (unsigned)__cvta_generic_to_shared(p);
    asm volatile(
        "ldmatrix.sync.aligned.m8n8.x4.shared.b16 {%0,%1,%2,%3}, [%4];\n"
        : "=r"(r0), "=r"(r1), "=r"(r2), "=r"(r3) : "r"(addr));
}

__device__ __forceinline__ void cp16(void* smem, const void* gmem) {
    unsigned s = (unsigned)__cvta_generic_to_shared(smem);
    asm volatile("cp.async.cg.shared.global [%0], [%1], 16;\n"
                 :: "r"(s), "l"(gmem) : "memory");
}

// ---------------------------------------------------------------------------
__global__ void cvt_f32_h(const float* __restrict__ in,
                          __half* __restrict__ out, int n8)
{
    int i = blockIdx.x * blockDim.x + threadIdx.x;
    if (i >= n8) return;
    const float4* p = reinterpret_cast<const float4*>(in) + (size_t)i * 2;
    float4 v0 = p[0], v1 = p[1];
    uint4 u;
    u.x = pack_h2(v0.x, v0.y);
    u.y = pack_h2(v0.z, v0.w);
    u.z = pack_h2(v1.x, v1.y);
    u.w = pack_h2(v1.z, v1.w);
    reinterpret_cast<uint4*>(out)[i] = u;
}

__global__ void transpose_w_h(const float* __restrict__ W,
                              __half* __restrict__ WT, int K, int N)
{
    __shared__ float tile[32][33];
    const int k0 = blockIdx.x * 32, n0 = blockIdx.y * 32;
    for (int i = threadIdx.y; i < 32; i += 8)
        tile[i][threadIdx.x] = W[(size_t)(k0 + i) * N + n0 + threadIdx.x];
    __syncthreads();
    for (int i = threadIdx.y; i < 32; i += 8)
        WT[(size_t)(n0 + i) * K + k0 + threadIdx.x] =
            __float2half_rn(tile[threadIdx.x][i]);
}

__global__ __launch_bounds__(256) void transpose_v_h(
    const __half* __restrict__ qkvh, __half* __restrict__ vt)
{
    __shared__ __half tile[128][72];
    const int bh = blockIdx.y;
    const int b = bh >> 4, h = bh & 15;
    const int m0 = blockIdx.x * 128;
    const __half* vb = qkvh + (size_t)b * NN * 3 * CC + 2 * CC + h * DD;

#pragma unroll
    for (int it = 0; it < 4; it++) {
        const int idx = threadIdx.x + 256 * it;
        const int m = idx >> 3, c8 = idx & 7;
        uint4 v = *reinterpret_cast<const uint4*>(
            vb + (size_t)(m0 + m) * 3 * CC + c8 * 8);
        *reinterpret_cast<uint4*>(&tile[m][c8 * 8]) = v;
    }
    __syncthreads();
    __half* ob = vt + (size_t)bh * DD * NN + m0;
#pragma unroll
    for (int it = 0; it < 4; it++) {
        const int idx = threadIdx.x + 256 * it;
        const int d = idx >> 4, mc = idx & 15;
        __half hbuf[8];
#pragma unroll
        for (int j = 0; j < 8; j++) hbuf[j] = tile[mc * 8 + j][d];
        *reinterpret_cast<uint4*>(ob + (size_t)d * NN + mc * 8) =
            *reinterpret_cast<uint4*>(hbuf);
    }
}

// ---------------------------------------------------------------------------
// fp16 TC GEMM + bias (unchanged from R12, tail-safe cp.async ring).
// ---------------------------------------------------------------------------
__global__ __launch_bounds__(256, 2) void gemm_h3(
    const __half* __restrict__ Ah, const __half* __restrict__ BT,
    const float* __restrict__ bias, void* __restrict__ Cout,
    int M, int N, int K, int out_half)
{
    extern __shared__ __align__(16) char dsm[];
    char* sA = dsm;
    char* sB = dsm + 3 * 10240;

    const int tid  = threadIdx.x;
    const int brow = blockIdx.y * 128;
    const int bcol = blockIdx.x * 128;
    const int w = tid >> 5, l = tid & 31;
    const int wr = w >> 2, wc = w & 3;
    const int g = l >> 2, t = l & 3;

    const int arow = l & 15;
    const int acol = (l >> 4) * 8;
    const int brow8 = ((l >> 4) * 8) + (l & 7);
    const int bcol8 = ((l >> 3) & 1) * 8;

    auto cp_stage = [&](int kc, int st) {
        const int k0 = kc << 5;
#pragma unroll
        for (int j = 0; j < 2; j++) {
            const int i = tid + 256 * j;
            const int r = i >> 2, c = i & 3;
            cp16(sA + st * 10240 + r * 80 + c * 16,
                 Ah + (size_t)(brow + r) * K + k0 + c * 8);
        }
#pragma unroll
        for (int j = 0; j < 2; j++) {
            const int i = tid + 256 * j;
            const int r = i >> 2, c = i & 3;
            cp16(sB + st * 10240 + r * 80 + c * 16,
                 BT + (size_t)(bcol + r) * K + k0 + c * 8);
        }
        asm volatile("cp.async.commit_group;\n" ::: "memory");
    };

    float acc[4][4][4];
#pragma unroll
    for (int i = 0; i < 4; i++)
#pragma unroll
        for (int j = 0; j < 4; j++)
#pragma unroll
            for (int r = 0; r < 4; r++) acc[i][j][r] = 0.0f;

    const int nIter = K >> 5;
    cp_stage(0, 0);
    cp_stage(1, 1);
    for (int it = 0; it < nIter; it++) {
        if (it + 1 < nIter)
            asm volatile("cp.async.wait_group 1;\n" ::: "memory");
        else
            asm volatile("cp.async.wait_group 0;\n" ::: "memory");
        __syncthreads();
        const int st = it % 3;
        const __half* pA = reinterpret_cast<const __half*>(sA + st * 10240);
        const __half* pB = reinterpret_cast<const __half*>(sB + st * 10240);
#pragma unroll
        for (int ss = 0; ss < 2; ss++) {
            const int kk = ss * 16;
            unsigned a[4][4], b[4][2];
#pragma unroll
            for (int i = 0; i < 4; i++)
                ldmx4(a[i][0], a[i][1], a[i][2], a[i][3],
                      pA + (wr * 64 + i * 16 + arow) * 40 + kk + acol);
#pragma unroll
            for (int jp = 0; jp < 2; jp++)
                ldmx4(b[jp * 2][0], b[jp * 2][1],
                      b[jp * 2 + 1][0], b[jp * 2 + 1][1],
                      pB + (wc * 32 + jp * 16 + brow8) * 40 + kk + bcol8);
#pragma unroll
            for (int i = 0; i < 4; i++)
#pragma unroll
                for (int j = 0; j < 4; j++)
                    mma_f16(acc[i][j], a[i][0], a[i][1], a[i][2], a[i][3],
                            b[j][0], b[j][1]);
        }
        if (it + 2 < nIter) cp_stage(it + 2, (it + 2) % 3);
    }

    if (out_half) {
        __half* C = reinterpret_cast<__half*>(Cout);
#pragma unroll
        for (int j = 0; j < 4; j++) {
            const int col = bcol + wc * 32 + j * 8 + 2 * t;
            const float b0 = bias[col], b1 = bias[col + 1];
#pragma unroll
            for (int i = 0; i < 4; i++) {
                const int r0 = brow + wr * 64 + i * 16;
                *reinterpret_cast<unsigned*>(&C[(size_t)(r0 + g) * N + col]) =
                    pack_h2(acc[i][j][0] + b0, acc[i][j][1] + b1);
                *reinterpret_cast<unsigned*>(&C[(size_t)(r0 + g + 8) * N + col]) =
                    pack_h2(acc[i][j][2] + b0, acc[i][j][3] + b1);
            }
        }
    } else {
        float* C = reinterpret_cast<float*>(Cout);
#pragma unroll
        for (int j = 0; j < 4; j++) {
            const int col = bcol + wc * 32 + j * 8 + 2 * t;
            const float b0 = bias[col], b1 = bias[col + 1];
#pragma unroll
            for (int i = 0; i < 4; i++) {
                const int r0 = brow + wr * 64 + i * 16;
                float2 o0 = {acc[i][j][0] + b0, acc[i][j][1] + b1};
                float2 o1 = {acc[i][j][2] + b0, acc[i][j][3] + b1};
                *reinterpret_cast<float2*>(&C[(size_t)(r0 + g) * N + col]) = o0;
                *reinterpret_cast<float2*>(&C[(size_t)(r0 + g + 8) * N + col]) = o1;
            }
        }
    }
}

// ---------------------------------------------------------------------------
// Fully fused attention (R13 structure: 32 rows, 512 thr), with the attn
// store folded INTO the PV loop so STGs overlap mma.
// Dyn smem (phases overlay): Qs[32][72] | Ks[3][128][72] = 59904 B;
// PV Vs[2][64][136]=34816; red [8][8][32] float4 = 32768.
// ---------------------------------------------------------------------------
__global__ __launch_bounds__(512) void attn_fused_h(
    const __half* __restrict__ qkvh, const __half* __restrict__ vt,
    float* __restrict__ attn, __half* __restrict__ ctxh)
{
    extern __shared__ __align__(16) char dyn[];
    __half* Qs = reinterpret_cast<__half*>(dyn);            // [32][72]
    __half* Ks = Qs + 32 * 72;                              // [3][128][72]
    __half* Vs = reinterpret_cast<__half*>(dyn);            // [2][64][136]
    float4* redO = reinterpret_cast<float4*>(dyn);          // [8][8][32]
    __shared__ float redM[32 * 9];
    __shared__ float redS[32 * 9];

    const int bh = blockIdx.y;
    const int b = bh >> 4, h = bh & 15;
    const int n0 = blockIdx.x * FROWS;

    const int tid = threadIdx.x;
    const int w = tid >> 5, l = tid & 31;
    const int g = l >> 2, t = l & 3;
    const int wr = w >> 3, wc = w & 7;

    const int arow = l & 15;
    const int acol = (l >> 4) * 8;
    const int brow8 = ((l >> 4) * 8) + (l & 7);
    const int bcol8 = ((l >> 3) & 1) * 8;

    const __half* qb = qkvh + (size_t)b * NN * 3 * CC + h * DD;
    const __half* kb = qb + CC;
    const __half* vb = vt + (size_t)bh * DD * NN;

    // ---------------- Phase 1: QK^T ----------------
    auto cp_k = [&](int c, int st) {
        const int m0 = c * 128;
#pragma unroll
        for (int j = 0; j < 2; j++) {
            const int idx = tid * 2 + j;
            const int m = idx >> 3, c8 = idx & 7;
            cp16(Ks + (st * 128 + m) * 72 + c8 * 8,
                 kb + (size_t)(m0 + m) * 3 * CC + c8 * 8);
        }
        asm volatile("cp.async.commit_group;\n" ::: "memory");
    };

    cp_k(0, 0);
    cp_k(1, 1);

    if (tid < 256) {
        const int row = tid >> 3, c8 = tid & 7;
        *reinterpret_cast<uint4*>(Qs + row * 72 + c8 * 8) =
            *reinterpret_cast<const uint4*>(qb + (size_t)(n0 + row) * 3 * CC + c8 * 8);
    }
    __syncthreads();

    unsigned qa[4][4];
#pragma unroll
    for (int ss = 0; ss < 4; ss++)
        ldmx4(qa[ss][0], qa[ss][1], qa[ss][2], qa[ss][3],
              Qs + (wr * 16 + arow) * 72 + ss * 16 + acol);

    float acc[8][2][4];
#pragma unroll
    for (int c = 0; c < 8; c++)
#pragma unroll
        for (int jn = 0; jn < 2; jn++)
#pragma unroll
            for (int r = 0; r < 4; r++) acc[c][jn][r] = 0.0f;

    const int row0 = wr * 16 + g;
    const int row1 = row0 + 8;

#pragma unroll
    for (int c = 0; c < 8; c++) {
        if (c + 1 < 8)
            asm volatile("cp.async.wait_group 1;\n" ::: "memory");
        else
            asm volatile("cp.async.wait_group 0;\n" ::: "memory");
        __syncthreads();
        const int st = c % 3;
#pragma unroll
        for (int ss = 0; ss < 4; ss++) {
            const int kk = ss * 16;
            unsigned kb0, kb1, kb2, kb3;
            ldmx4(kb0, kb1, kb2, kb3,
                  Ks + (st * 128 + wc * 16 + brow8) * 72 + kk + bcol8);
            mma_f16(acc[c][0], qa[ss][0], qa[ss][1], qa[ss][2], qa[ss][3], kb0, kb1);
            mma_f16(acc[c][1], qa[ss][0], qa[ss][1], qa[ss][2], qa[ss][3], kb2, kb3);
        }
        if (c + 2 < 8) cp_k(c + 2, (c + 2) % 3);
    }

    // ---------------- Phase 2: softmax ----------------
#pragma unroll
    for (int c = 0; c < 8; c++)
#pragma unroll
        for (int jn = 0; jn < 2; jn++)
#pragma unroll
            for (int r = 0; r < 4; r++) acc[c][jn][r] *= SCALE;

    float mx0 = -3.402823466e+38f, mx1 = -3.402823466e+38f;
#pragma unroll
    for (int c = 0; c < 8; c++)
#pragma unroll
        for (int jn = 0; jn < 2; jn++) {
            mx0 = fmaxf(mx0, fmaxf(acc[c][jn][0], acc[c][jn][1]));
            mx1 = fmaxf(mx1, fmaxf(acc[c][jn][2], acc[c][jn][3]));
        }
#pragma unroll
    for (int o = 1; o <= 2; o <<= 1) {
        mx0 = fmaxf(mx0, __shfl_xor_sync(0xffffffffu, mx0, o));
        mx1 = fmaxf(mx1, __shfl_xor_sync(0xffffffffu, mx1, o));
    }
    if (t == 0) {
        redM[row0 * 9 + wc] = mx0;
        redM[row1 * 9 + wc] = mx1;
    }
    __syncthreads();
    mx0 = redM[row0 * 9];
    mx1 = redM[row1 * 9];
#pragma unroll
    for (int k = 1; k < 8; k++) {
        mx0 = fmaxf(mx0, redM[row0 * 9 + k]);
        mx1 = fmaxf(mx1, redM[row1 * 9 + k]);
    }

    float s0 = 0.0f, s1 = 0.0f;
#pragma unroll
    for (int c = 0; c < 8; c++)
#pragma unroll
        for (int jn = 0; jn < 2; jn++) {
            acc[c][jn][0] = __expf(acc[c][jn][0] - mx0);
            acc[c][jn][1] = __expf(acc[c][jn][1] - mx0);
            acc[c][jn][2] = __expf(acc[c][jn][2] - mx1);
            acc[c][jn][3] = __expf(acc[c][jn][3] - mx1);
            s0 += acc[c][jn][0] + acc[c][jn][1];
            s1 += acc[c][jn][2] + acc[c][jn][3];
        }
#pragma unroll
    for (int o = 1; o <= 2; o <<= 1) {
        s0 += __shfl_xor_sync(0xffffffffu, s0, o);
        s1 += __shfl_xor_sync(0xffffffffu, s1, o);
    }
    if (t == 0) {
        redS[row0 * 9 + wc] = s0;
        redS[row1 * 9 + wc] = s1;
    }
    __syncthreads();
    s0 = redS[row0 * 9];
    s1 = redS[row1 * 9];
#pragma unroll
    for (int k = 1; k < 8; k++) {
        s0 += redS[row0 * 9 + k];
        s1 += redS[row1 * 9 + k];
    }
    const float inv0 = 1.0f / s0;
    const float inv1 = 1.0f / s1;

#pragma unroll
    for (int c = 0; c < 8; c++)
#pragma unroll
        for (int jn = 0; jn < 2; jn++) {
            acc[c][jn][0] *= inv0;
            acc[c][jn][1] *= inv0;
            acc[c][jn][2] *= inv1;
            acc[c][jn][3] *= inv1;
        }

    // ---------------- Phase 3+4: PV with interleaved attn stores ----------
    float oacc[8][4];
#pragma unroll
    for (int j = 0; j < 8; j++)
#pragma unroll
        for (int r = 0; r < 4; r++) oacc[j][r] = 0.0f;

    uint4 vpre[2];
    auto ldg_v = [&](int c) {
#pragma unroll
        for (int j = 0; j < 2; j++) {
            const int idx = tid + 512 * j;
            const int d = idx >> 4, k8 = idx & 15;
            vpre[j] = *reinterpret_cast<const uint4*>(
                vb + (size_t)d * NN + c * 128 + k8 * 8);
        }
    };
    auto sts_v = [&](int st) {
#pragma unroll
        for (int j = 0; j < 2; j++) {
            const int idx = tid + 512 * j;
            const int d = idx >> 4, k8 = idx & 15;
            *reinterpret_cast<uint4*>(Vs + (st * 64 + d) * 136 + k8 * 8) = vpre[j];
        }
    };

    float* arow0 = attn + ((size_t)bh * NN + n0 + row0) * NN;
    float* arow1 = attn + ((size_t)bh * NN + n0 + row1) * NN;

    __syncthreads();    // all QK smem reads done; Vs overlays Qs/Ks
    ldg_v(0);
    sts_v(0);
    __syncthreads();
#pragma unroll
    for (int c = 0; c < 8; c++) {
        if (c + 1 < 8) ldg_v(c + 1);
        const int st = c & 1;
        const unsigned pa0 = pack_h2(acc[c][0][0], acc[c][0][1]);
        const unsigned pa1 = pack_h2(acc[c][0][2], acc[c][0][3]);
        const unsigned pa2 = pack_h2(acc[c][1][0], acc[c][1][1]);
        const unsigned pa3 = pack_h2(acc[c][1][2], acc[c][1][3]);

        // attn stores for chunk c — overlap with the mma below
#pragma unroll
        for (int jn = 0; jn < 2; jn++) {
            const int col = c * 128 + wc * 16 + jn * 8 + 2 * t;
            float2 o0 = {acc[c][jn][0], acc[c][jn][1]};
            float2 o1 = {acc[c][jn][2], acc[c][jn][3]};
            *reinterpret_cast<float2*>(&arow0[col]) = o0;
            *reinterpret_cast<float2*>(&arow1[col]) = o1;
        }

        unsigned bf[8][2];
#pragma unroll
        for (int jp = 0; jp < 4; jp++)
            ldmx4(bf[jp * 2][0], bf[jp * 2][1],
                  bf[jp * 2 + 1][0], bf[jp * 2 + 1][1],
                  Vs + (st * 64 + jp * 16 + brow8) * 136 + wc * 16 + bcol8);
#pragma unroll
        for (int j = 0; j < 8; j++)
            mma_f16(oacc[j], pa0, pa1, pa2, pa3, bf[j][0], bf[j][1]);
        if (c + 1 < 8) { sts_v((c + 1) & 1); __syncthreads(); }
    }

    // ---------------- Phase 5: cross-warp (wc) reduction ----------------
    __syncthreads();    // PV reads of Vs done; redO overlays Vs
    if (wc >= 4) {
        const int area = wr * 4 + (wc - 4);
#pragma unroll
        for (int j = 0; j < 8; j++) {
            float4 v = {oacc[j][0], oacc[j][1], oacc[j][2], oacc[j][3]};
            redO[(area * 8 + j) * 32 + l] = v;
        }
    }
    __syncthreads();
    if (wc < 4) {
        const int area = wr * 4 + wc;
#pragma unroll
        for (int j = 0; j < 8; j++) {
            float4 v = redO[(area * 8 + j) * 32 + l];
            oacc[j][0] += v.x; oacc[j][1] += v.y;
            oacc[j][2] += v.z; oacc[j][3] += v.w;
        }
    }
    __syncthreads();
    if (wc >= 2 && wc < 4) {
        const int area = wr * 2 + (wc - 2);
#pragma unroll
        for (int j = 0; j < 8; j++) {
            float4 v = {oacc[j][0], oacc[j][1], oacc[j][2], oacc[j][3]};
            redO[(area * 8 + j) * 32 + l] = v;
        }
    }
    __syncthreads();
    if (wc < 2) {
        const int area = wr * 2 + wc;
#pragma unroll
        for (int j = 0; j < 8; j++) {
            float4 v = redO[(area * 8 + j) * 32 + l];
            oacc[j][0] += v.x; oacc[j][1] += v.y;
            oacc[j][2] += v.z; oacc[j][3] += v.w;
        }
    }
    __syncthreads();
    if (wc == 1) {
#pragma unroll
        for (int j = 0; j < 8; j++) {
            float4 v = {oacc[j][0], oacc[j][1], oacc[j][2], oacc[j][3]};
            redO[(wr * 8 + j) * 32 + l] = v;
        }
    }
    __syncthreads();
    if (wc == 0) {
#pragma unroll
        for (int j = 0; j < 8; j++) {
            float4 v = redO[(wr * 8 + j) * 32 + l];
            oacc[j][0] += v.x; oacc[j][1] += v.y;
            oacc[j][2] += v.z; oacc[j][3] += v.w;
        }
        const int r0 = n0 + wr * 16 + g;
#pragma unroll
        for (int j = 0; j < 8; j++) {
            const int col = h * DD + j * 8 + 2 * t;
            *reinterpret_cast<unsigned*>(
                &ctxh[((size_t)b * NN + r0) * CC + col]) =
                pack_h2(oacc[j][0], oacc[j][1]);
            *reinterpret_cast<unsigned*>(
                &ctxh[((size_t)b * NN + r0 + 8) * CC + col]) =
                pack_h2(oacc[j][2], oacc[j][3]);
        }
    }
}

// ---------------------------------------------------------------------------
extern "C" void kernel_launch(void* const* d_in, const int* in_sizes, int n_in,
                              void* d_out, int out_size)
{
    (void)in_sizes; (void)n_in; (void)out_size;
    const float* x      = (const float*)d_in[0];
    const float* w_qkv  = (const float*)d_in[1];
    const float* b_qkv  = (const float*)d_in[2];
    const float* w_proj = (const float*)d_in[3];
    const float* b_proj = (const float*)d_in[4];

    float* out  = (float*)d_out;
    float* attn = out + (size_t)BB * NN * CC;

    __half *xh, *qkvh, *ctxh, *wqkvT, *wprojT, *vt;
    cudaGetSymbolAddress((void**)&xh, g_xh);
    cudaGetSymbolAddress((void**)&qkvh, g_qkvh);
    cudaGetSymbolAddress((void**)&ctxh, g_ctxh);
    cudaGetSymbolAddress((void**)&wqkvT, g_wqkvT);
    cudaGetSymbolAddress((void**)&wprojT, g_wprojT);
    cudaGetSymbolAddress((void**)&vt, g_vt);

    const int g_smem = 6 * 10240;                     // 61440
    const int a_smem = (32 * 72 + 3 * 128 * 72) * 2;  // 59904
    cudaFuncSetAttribute(gemm_h3,
        cudaFuncAttributeMaxDynamicSharedMemorySize, g_smem);
    cudaFuncSetAttribute(attn_fused_h,
        cudaFuncAttributeMaxDynamicSharedMemorySize, a_smem);

    // 0) One-time conversions
    const int nx8 = BB * NN * CC / 8;
    cvt_f32_h<<<(nx8 + 255) / 256, 256>>>(x, xh, nx8);
    transpose_w_h<<<dim3(CC / 32, 3 * CC / 32), dim3(32, 8)>>>(
        w_qkv, wqkvT, CC, 3 * CC);
    transpose_w_h<<<dim3(CC / 32, CC / 32), dim3(32, 8)>>>(
        w_proj, wprojT, CC, CC);

    // 1) QKV projection (fp16 out)
    gemm_h3<<<dim3(3 * CC / 128, BB * NN / 128), 256, g_smem>>>(
        xh, wqkvT, b_qkv, qkvh, BB * NN, 3 * CC, CC, 1);

    // 1b) V transpose -> [bh][d][m]
    transpose_v_h<<<dim3(NN / 128, BB * HH), 256>>>(qkvh, vt);

    // 2) Fully fused attention (32 rows/CTA, attn stores inside PV loop)
    attn_fused_h<<<dim3(NN / FROWS, BB * HH), 512, a_smem>>>(
        qkvh, vt, attn, ctxh);

    // 3) Output projection (fp32 out)
    gemm_h3<<<dim3(CC / 128, BB * NN / 128), 256, g_smem>>>(
        ctxh, wprojT, b_proj, out, BB * NN, CC, CC, 0);
}

// round 16
// speedup vs baseline: 1.0893x; 1.0008x over previous
#include <cuda_runtime.h>
#include <cuda_fp16.h>
#include <cstdint>
#include <cstddef>

// B=8, N=1024, C=1024, H=16, D=64, scale = 0.125
#define BB 8
#define NN 1024
#define CC 1024
#define HH 16
#define DD 64
#define SCALE 0.125f
#define FROWS 32

__device__ __half g_xh[(size_t)BB * NN * CC];
__device__ __half g_qkvh[(size_t)BB * NN * 3 * CC];    // (B,N,3,H,D)
__device__ __half g_ctxh[(size_t)BB * NN * CC];
__device__ __half g_wqkvT[(size_t)3 * CC * CC];        // [n][k]
__device__ __half g_wprojT[(size_t)CC * CC];           // [n][k]
__device__ __half g_vt[(size_t)BB * HH * DD * NN];     // [bh][d][m]

__device__ __forceinline__ unsigned pack_h2(float a, float b) {
    __half2 h = __floats2half2_rn(a, b);
    return *reinterpret_cast<unsigned*>(&h);
}

__device__ __forceinline__ void mma_f16(float c[4],
    unsigned a0, unsigned a1, unsigned a2, unsigned a3,
    unsigned b0, unsigned b1)
{
    asm volatile(
        "mma.sync.aligned.m16n8k16.row.col.f32.f16.f16.f32 "
        "{%0,%1,%2,%3}, {%4,%5,%6,%7}, {%8,%9}, {%0,%1,%2,%3};\n"
        : "+f"(c[0]), "+f"(c[1]), "+f"(c[2]), "+f"(c[3])
        : "r"(a0), "r"(a1), "r"(a2), "r"(a3), "r"(b0), "r"(b1));
}

__device__ __forceinline__ void ldmx4(unsigned& r0, unsigned& r1,
                                      unsigned& r2, unsigned& r3,
                                      const void* p)
{
    unsigned addr = (unsigned)__cvta_generic_to_shared(p);
    asm volatile(
        "ldmatrix.sync.aligned.m8n8.x4.shared.b16 {%0,%1,%2,%3}, [%4];\n"
        : "=r"(r0), "=r"(r1), "=r"(r2), "=r"(r3) : "r"(addr));
}

__device__ __forceinline__ void cp16(void* smem, const void* gmem) {
    unsigned s = (unsigned)__cvta_generic_to_shared(smem);
    asm volatile("cp.async.cg.shared.global [%0], [%1], 16;\n"
                 :: "r"(s), "l"(gmem) : "memory");
}

// ---------------------------------------------------------------------------
// One-launch prep: x -> fp16 | w_qkv -> [n][k] fp16 | w_proj -> [n][k] fp16
// Grid: [0,4096) cvt x | [4096,7168) wqkv tiles | [7168,8192) wproj tiles
// ---------------------------------------------------------------------------
__global__ __launch_bounds__(256) void prep_all(
    const float* __restrict__ x, __half* __restrict__ xh,
    const float* __restrict__ w_qkv, __half* __restrict__ wqkvT,
    const float* __restrict__ w_proj, __half* __restrict__ wprojT)
{
    __shared__ float tile[32][33];
    const int bid = blockIdx.x;
    const int tid = threadIdx.x;

    if (bid < 4096) {
        const int i = bid * 256 + tid;          // n8 = 1048576 exactly
        const float4* p = reinterpret_cast<const float4*>(x) + (size_t)i * 2;
        float4 v0 = p[0], v1 = p[1];
        uint4 u;
        u.x = pack_h2(v0.x, v0.y);
        u.y = pack_h2(v0.z, v0.w);
        u.z = pack_h2(v1.x, v1.y);
        u.w = pack_h2(v1.z, v1.w);
        reinterpret_cast<uint4*>(xh)[i] = u;
        return;
    }

    const float* W;
    __half* WT;
    int N, tb;
    if (bid < 7168) { tb = bid - 4096; W = w_qkv;  WT = wqkvT;  N = 3 * CC; }
    else            { tb = bid - 7168; W = w_proj; WT = wprojT; N = CC;     }
    const int K = CC;
    const int k0 = (tb & 31) * 32;
    const int n0 = (tb >> 5) * 32;
    const int tx = tid & 31, ty = tid >> 5;

    for (int i = ty; i < 32; i += 8)
        tile[i][tx] = W[(size_t)(k0 + i) * N + n0 + tx];
    __syncthreads();
    for (int i = ty; i < 32; i += 8)
        WT[(size_t)(n0 + i) * K + k0 + tx] = __float2half_rn(tile[tx][i]);
}

__global__ __launch_bounds__(256) void transpose_v_h(
    const __half* __restrict__ qkvh, __half* __restrict__ vt)
{
    __shared__ __half tile[128][72];
    const int bh = blockIdx.y;
    const int b = bh >> 4, h = bh & 15;
    const int m0 = blockIdx.x * 128;
    const __half* vb = qkvh + (size_t)b * NN * 3 * CC + 2 * CC + h * DD;

#pragma unroll
    for (int it = 0; it < 4; it++) {
        const int idx = threadIdx.x + 256 * it;
        const int m = idx >> 3, c8 = idx & 7;
        uint4 v = *reinterpret_cast<const uint4*>(
            vb + (size_t)(m0 + m) * 3 * CC + c8 * 8);
        *reinterpret_cast<uint4*>(&tile[m][c8 * 8]) = v;
    }
    __syncthreads();
    __half* ob = vt + (size_t)bh * DD * NN + m0;
#pragma unroll
    for (int it = 0; it < 4; it++) {
        const int idx = threadIdx.x + 256 * it;
        const int d = idx >> 4, mc = idx & 15;
        __half hbuf[8];
#pragma unroll
        for (int j = 0; j < 8; j++) hbuf[j] = tile[mc * 8 + j][d];
        *reinterpret_cast<uint4*>(ob + (size_t)d * NN + mc * 8) =
            *reinterpret_cast<uint4*>(hbuf);
    }
}

// ---------------------------------------------------------------------------
// fp16 TC GEMM + bias (unchanged: tail-safe cp.async ring, 2 CTAs/SM).
// ---------------------------------------------------------------------------
__global__ __launch_bounds__(256, 2) void gemm_h3(
    const __half* __restrict__ Ah, const __half* __restrict__ BT,
    const float* __restrict__ bias, void* __restrict__ Cout,
    int M, int N, int K, int out_half)
{
    extern __shared__ __align__(16) char dsm[];
    char* sA = dsm;
    char* sB = dsm + 3 * 10240;

    const int tid  = threadIdx.x;
    const int brow = blockIdx.y * 128;
    const int bcol = blockIdx.x * 128;
    const int w = tid >> 5, l = tid & 31;
    const int wr = w >> 2, wc = w & 3;
    const int g = l >> 2, t = l & 3;

    const int arow = l & 15;
    const int acol = (l >> 4) * 8;
    const int brow8 = ((l >> 4) * 8) + (l & 7);
    const int bcol8 = ((l >> 3) & 1) * 8;

    auto cp_stage = [&](int kc, int st) {
        const int k0 = kc << 5;
#pragma unroll
        for (int j = 0; j < 2; j++) {
            const int i = tid + 256 * j;
            const int r = i >> 2, c = i & 3;
            cp16(sA + st * 10240 + r * 80 + c * 16,
                 Ah + (size_t)(brow + r) * K + k0 + c * 8);
        }
#pragma unroll
        for (int j = 0; j < 2; j++) {
            const int i = tid + 256 * j;
            const int r = i >> 2, c = i & 3;
            cp16(sB + st * 10240 + r * 80 + c * 16,
                 BT + (size_t)(bcol + r) * K + k0 + c * 8);
        }
        asm volatile("cp.async.commit_group;\n" ::: "memory");
    };

    float acc[4][4][4];
#pragma unroll
    for (int i = 0; i < 4; i++)
#pragma unroll
        for (int j = 0; j < 4; j++)
#pragma unroll
            for (int r = 0; r < 4; r++) acc[i][j][r] = 0.0f;

    const int nIter = K >> 5;
    cp_stage(0, 0);
    cp_stage(1, 1);
    for (int it = 0; it < nIter; it++) {
        if (it + 1 < nIter)
            asm volatile("cp.async.wait_group 1;\n" ::: "memory");
        else
            asm volatile("cp.async.wait_group 0;\n" ::: "memory");
        __syncthreads();
        const int st = it % 3;
        const __half* pA = reinterpret_cast<const __half*>(sA + st * 10240);
        const __half* pB = reinterpret_cast<const __half*>(sB + st * 10240);
#pragma unroll
        for (int ss = 0; ss < 2; ss++) {
            const int kk = ss * 16;
            unsigned a[4][4], b[4][2];
#pragma unroll
            for (int i = 0; i < 4; i++)
                ldmx4(a[i][0], a[i][1], a[i][2], a[i][3],
                      pA + (wr * 64 + i * 16 + arow) * 40 + kk + acol);
#pragma unroll
            for (int jp = 0; jp < 2; jp++)
                ldmx4(b[jp * 2][0], b[jp * 2][1],
                      b[jp * 2 + 1][0], b[jp * 2 + 1][1],
                      pB + (wc * 32 + jp * 16 + brow8) * 40 + kk + bcol8);
#pragma unroll
            for (int i = 0; i < 4; i++)
#pragma unroll
                for (int j = 0; j < 4; j++)
                    mma_f16(acc[i][j], a[i][0], a[i][1], a[i][2], a[i][3],
                            b[j][0], b[j][1]);
        }
        if (it + 2 < nIter) cp_stage(it + 2, (it + 2) % 3);
    }

    if (out_half) {
        __half* C = reinterpret_cast<__half*>(Cout);
#pragma unroll
        for (int j = 0; j < 4; j++) {
            const int col = bcol + wc * 32 + j * 8 + 2 * t;
            const float b0 = bias[col], b1 = bias[col + 1];
#pragma unroll
            for (int i = 0; i < 4; i++) {
                const int r0 = brow + wr * 64 + i * 16;
                *reinterpret_cast<unsigned*>(&C[(size_t)(r0 + g) * N + col]) =
                    pack_h2(acc[i][j][0] + b0, acc[i][j][1] + b1);
                *reinterpret_cast<unsigned*>(&C[(size_t)(r0 + g + 8) * N + col]) =
                    pack_h2(acc[i][j][2] + b0, acc[i][j][3] + b1);
            }
        }
    } else {
        float* C = reinterpret_cast<float*>(Cout);
#pragma unroll
        for (int j = 0; j < 4; j++) {
            const int col = bcol + wc * 32 + j * 8 + 2 * t;
            const float b0 = bias[col], b1 = bias[col + 1];
#pragma unroll
            for (int i = 0; i < 4; i++) {
                const int r0 = brow + wr * 64 + i * 16;
                float2 o0 = {acc[i][j][0] + b0, acc[i][j][1] + b1};
                float2 o1 = {acc[i][j][2] + b0, acc[i][j][3] + b1};
                *reinterpret_cast<float2*>(&C[(size_t)(r0 + g) * N + col]) = o0;
                *reinterpret_cast<float2*>(&C[(size_t)(r0 + g + 8) * N + col]) = o1;
            }
        }
    }
}

// ---------------------------------------------------------------------------
// Fully fused attention (32 rows, 512 thr). Disjoint smem regions:
//   Qs[32][72] | Ks[3][128][72] | Vs[3][64][136] | redO[8][8][32]f4 = 144896 B
// V prefetched via its own cp.async ring during softmax; attn stores inside
// the PV loop (overlap mma).
// ---------------------------------------------------------------------------
__global__ __launch_bounds__(512) void attn_fused_h(
    const __half* __restrict__ qkvh, const __half* __restrict__ vt,
    float* __restrict__ attn, __half* __restrict__ ctxh)
{
    extern __shared__ __align__(16) char dyn[];
    __half* Qs = reinterpret_cast<__half*>(dyn);            // [32][72]
    __half* Ks = Qs + 32 * 72;                              // [3][128][72]
    __half* Vs = Ks + 3 * 128 * 72;                         // [3][64][136]
    float4* redO = reinterpret_cast<float4*>(dyn + 112128); // [8][8][32]
    __shared__ float redM[32 * 9];
    __shared__ float redS[32 * 9];

    const int bh = blockIdx.y;
    const int b = bh >> 4, h = bh & 15;
    const int n0 = blockIdx.x * FROWS;

    const int tid = threadIdx.x;
    const int w = tid >> 5, l = tid & 31;
    const int g = l >> 2, t = l & 3;
    const int wr = w >> 3, wc = w & 7;

    const int arow = l & 15;
    const int acol = (l >> 4) * 8;
    const int brow8 = ((l >> 4) * 8) + (l & 7);
    const int bcol8 = ((l >> 3) & 1) * 8;

    const __half* qb = qkvh + (size_t)b * NN * 3 * CC + h * DD;
    const __half* kb = qb + CC;
    const __half* vb = vt + (size_t)bh * DD * NN;

    // ---------------- Phase 1: QK^T ----------------
    auto cp_k = [&](int c, int st) {
        const int m0 = c * 128;
#pragma unroll
        for (int j = 0; j < 2; j++) {
            const int idx = tid * 2 + j;
            const int m = idx >> 3, c8 = idx & 7;
            cp16(Ks + (st * 128 + m) * 72 + c8 * 8,
                 kb + (size_t)(m0 + m) * 3 * CC + c8 * 8);
        }
        asm volatile("cp.async.commit_group;\n" ::: "memory");
    };
    auto cp_v = [&](int c, int st) {
#pragma unroll
        for (int j = 0; j < 2; j++) {
            const int idx = tid + 512 * j;
            const int d = idx >> 4, k8 = idx & 15;
            cp16(Vs + (st * 64 + d) * 136 + k8 * 8,
                 vb + (size_t)d * NN + c * 128 + k8 * 8);
        }
        asm volatile("cp.async.commit_group;\n" ::: "memory");
    };

    cp_k(0, 0);
    cp_k(1, 1);

    if (tid < 256) {
        const int row = tid >> 3, c8 = tid & 7;
        *reinterpret_cast<uint4*>(Qs + row * 72 + c8 * 8) =
            *reinterpret_cast<const uint4*>(qb + (size_t)(n0 + row) * 3 * CC + c8 * 8);
    }
    __syncthreads();

    unsigned qa[4][4];
#pragma unroll
    for (int ss = 0; ss < 4; ss++)
        ldmx4(qa[ss][0], qa[ss][1], qa[ss][2], qa[ss][3],
              Qs + (wr * 16 + arow) * 72 + ss * 16 + acol);

    float acc[8][2][4];
#pragma unroll
    for (int c = 0; c < 8; c++)
#pragma unroll
        for (int jn = 0; jn < 2; jn++)
#pragma unroll
            for (int r = 0; r < 4; r++) acc[c][jn][r] = 0.0f;

    const int row0 = wr * 16 + g;
    const int row1 = row0 + 8;

#pragma unroll
    for (int c = 0; c < 8; c++) {
        if (c + 1 < 8)
            asm volatile("cp.async.wait_group 1;\n" ::: "memory");
        else
            asm volatile("cp.async.wait_group 0;\n" ::: "memory");
        __syncthreads();
        const int st = c % 3;
#pragma unroll
        for (int ss = 0; ss < 4; ss++) {
            const int kk = ss * 16;
            unsigned kb0, kb1, kb2, kb3;
            ldmx4(kb0, kb1, kb2, kb3,
                  Ks + (st * 128 + wc * 16 + brow8) * 72 + kk + bcol8);
            mma_f16(acc[c][0], qa[ss][0], qa[ss][1], qa[ss][2], qa[ss][3], kb0, kb1);
            mma_f16(acc[c][1], qa[ss][0], qa[ss][1], qa[ss][2], qa[ss][3], kb2, kb3);
        }
        if (c + 2 < 8) cp_k(c + 2, (c + 2) % 3);
    }

    // Kick off V prefetch (own region) — covers the whole softmax phase.
    cp_v(0, 0);
    cp_v(1, 1);

    // ---------------- Phase 2: softmax ----------------
#pragma unroll
    for (int c = 0; c < 8; c++)
#pragma unroll
        for (int jn = 0; jn < 2; jn++)
#pragma unroll
            for (int r = 0; r < 4; r++) acc[c][jn][r] *= SCALE;

    float mx0 = -3.402823466e+38f, mx1 = -3.402823466e+38f;
#pragma unroll
    for (int c = 0; c < 8; c++)
#pragma unroll
        for (int jn = 0; jn < 2; jn++) {
            mx0 = fmaxf(mx0, fmaxf(acc[c][jn][0], acc[c][jn][1]));
            mx1 = fmaxf(mx1, fmaxf(acc[c][jn][2], acc[c][jn][3]));
        }
#pragma unroll
    for (int o = 1; o <= 2; o <<= 1) {
        mx0 = fmaxf(mx0, __shfl_xor_sync(0xffffffffu, mx0, o));
        mx1 = fmaxf(mx1, __shfl_xor_sync(0xffffffffu, mx1, o));
    }
    if (t == 0) {
        redM[row0 * 9 + wc] = mx0;
        redM[row1 * 9 + wc] = mx1;
    }
    __syncthreads();
    mx0 = redM[row0 * 9];
    mx1 = redM[row1 * 9];
#pragma unroll
    for (int k = 1; k < 8; k++) {
        mx0 = fmaxf(mx0, redM[row0 * 9 + k]);
        mx1 = fmaxf(mx1, redM[row1 * 9 + k]);
    }

    float s0 = 0.0f, s1 = 0.0f;
#pragma unroll
    for (int c = 0; c < 8; c++)
#pragma unroll
        for (int jn = 0; jn < 2; jn++) {
            acc[c][jn][0] = __expf(acc[c][jn][0] - mx0);
            acc[c][jn][1] = __expf(acc[c][jn][1] - mx0);
            acc[c][jn][2] = __expf(acc[c][jn][2] - mx1);
            acc[c][jn][3] = __expf(acc[c][jn][3] - mx1);
            s0 += acc[c][jn][0] + acc[c][jn][1];
            s1 += acc[c][jn][2] + acc[c][jn][3];
        }
#pragma unroll
    for (int o = 1; o <= 2; o <<= 1) {
        s0 += __shfl_xor_sync(0xffffffffu, s0, o);
        s1 += __shfl_xor_sync(0xffffffffu, s1, o);
    }
    if (t == 0) {
        redS[row0 * 9 + wc] = s0;
        redS[row1 * 9 + wc] = s1;
    }
    __syncthreads();
    s0 = redS[row0 * 9];
    s1 = redS[row1 * 9];
#pragma unroll
    for (int k = 1; k < 8; k++) {
        s0 += redS[row0 * 9 + k];
        s1 += redS[row1 * 9 + k];
    }
    const float inv0 = 1.0f / s0;
    const float inv1 = 1.0f / s1;

#pragma unroll
    for (int c = 0; c < 8; c++)
#pragma unroll
        for (int jn = 0; jn < 2; jn++) {
            acc[c][jn][0] *= inv0;
            acc[c][jn][1] *= inv0;
            acc[c][jn][2] *= inv1;
            acc[c][jn][3] *= inv1;
        }

    // ---------------- Phase 3+4: PV with interleaved attn stores ----------
    float oacc[8][4];
#pragma unroll
    for (int j = 0; j < 8; j++)
#pragma unroll
        for (int r = 0; r < 4; r++) oacc[j][r] = 0.0f;

    float* arow0 = attn + ((size_t)bh * NN + n0 + row0) * NN;
    float* arow1 = attn + ((size_t)bh * NN + n0 + row1) * NN;

#pragma unroll
    for (int c = 0; c < 8; c++) {
        if (c + 1 < 8)
            asm volatile("cp.async.wait_group 1;\n" ::: "memory");
        else
            asm volatile("cp.async.wait_group 0;\n" ::: "memory");
        __syncthreads();
        const int st = c % 3;
        const unsigned pa0 = pack_h2(acc[c][0][0], acc[c][0][1]);
        const unsigned pa1 = pack_h2(acc[c][0][2], acc[c][0][3]);
        const unsigned pa2 = pack_h2(acc[c][1][0], acc[c][1][1]);
        const unsigned pa3 = pack_h2(acc[c][1][2], acc[c][1][3]);

        // attn stores for chunk c — overlap with the mma below
#pragma unroll
        for (int jn = 0; jn < 2; jn++) {
            const int col = c * 128 + wc * 16 + jn * 8 + 2 * t;
            float2 o0 = {acc[c][jn][0], acc[c][jn][1]};
            float2 o1 = {acc[c][jn][2], acc[c][jn][3]};
            *reinterpret_cast<float2*>(&arow0[col]) = o0;
            *reinterpret_cast<float2*>(&arow1[col]) = o1;
        }

        unsigned bf[8][2];
#pragma unroll
        for (int jp = 0; jp < 4; jp++)
            ldmx4(bf[jp * 2][0], bf[jp * 2][1],
                  bf[jp * 2 + 1][0], bf[jp * 2 + 1][1],
                  Vs + (st * 64 + jp * 16 + brow8) * 136 + wc * 16 + bcol8);
#pragma unroll
        for (int j = 0; j < 8; j++)
            mma_f16(oacc[j], pa0, pa1, pa2, pa3, bf[j][0], bf[j][1]);
        if (c + 2 < 8) cp_v(c + 2, (c + 2) % 3);
    }

    // ---------------- Phase 5: cross-warp (wc) reduction ----------------
    if (wc >= 4) {
        const int area = wr * 4 + (wc - 4);
#pragma unroll
        for (int j = 0; j < 8; j++) {
            float4 v = {oacc[j][0], oacc[j][1], oacc[j][2], oacc[j][3]};
            redO[(area * 8 + j) * 32 + l] = v;
        }
    }
    __syncthreads();
    if (wc < 4) {
        const int area = wr * 4 + wc;
#pragma unroll
        for (int j = 0; j < 8; j++) {
            float4 v = redO[(area * 8 + j) * 32 + l];
            oacc[j][0] += v.x; oacc[j][1] += v.y;
            oacc[j][2] += v.z; oacc[j][3] += v.w;
        }
    }
    __syncthreads();
    if (wc >= 2 && wc < 4) {
        const int area = wr * 2 + (wc - 2);
#pragma unroll
        for (int j = 0; j < 8; j++) {
            float4 v = {oacc[j][0], oacc[j][1], oacc[j][2], oacc[j][3]};
            redO[(area * 8 + j) * 32 + l] = v;
        }
    }
    __syncthreads();
    if (wc < 2) {
        const int area = wr * 2 + wc;
#pragma unroll
        for (int j = 0; j < 8; j++) {
            float4 v = redO[(area * 8 + j) * 32 + l];
            oacc[j][0] += v.x; oacc[j][1] += v.y;
            oacc[j][2] += v.z; oacc[j][3] += v.w;
        }
    }
    __syncthreads();
    if (wc == 1) {
#pragma unroll
        for (int j = 0; j < 8; j++) {
            float4 v = {oacc[j][0], oacc[j][1], oacc[j][2], oacc[j][3]};
            redO[(wr * 8 + j) * 32 + l] = v;
        }
    }
    __syncthreads();
    if (wc == 0) {
#pragma unroll
        for (int j = 0; j < 8; j++) {
            float4 v = redO[(wr * 8 + j) * 32 + l];
            oacc[j][0] += v.x; oacc[j][1] += v.y;
            oacc[j][2] += v.z; oacc[j][3] += v.w;
        }
        const int r0 = n0 + wr * 16 + g;
#pragma unroll
        for (int j = 0; j < 8; j++) {
            const int col = h * DD + j * 8 + 2 * t;
            *reinterpret_cast<unsigned*>(
                &ctxh[((size_t)b * NN + r0) * CC + col]) =
                pack_h2(oacc[j][0], oacc[j][1]);
            *reinterpret_cast<unsigned*>(
                &ctxh[((size_t)b * NN + r0 + 8) * CC + col]) =
                pack_h2(oacc[j][2], oacc[j][3]);
        }
    }
}

// ---------------------------------------------------------------------------
extern "C" void kernel_launch(void* const* d_in, const int* in_sizes, int n_in,
                              void* d_out, int out_size)
{
    (void)in_sizes; (void)n_in; (void)out_size;
    const float* x      = (const float*)d_in[0];
    const float* w_qkv  = (const float*)d_in[1];
    const float* b_qkv  = (const float*)d_in[2];
    const float* w_proj = (const float*)d_in[3];
    const float* b_proj = (const float*)d_in[4];

    float* out  = (float*)d_out;
    float* attn = out + (size_t)BB * NN * CC;

    __half *xh, *qkvh, *ctxh, *wqkvT, *wprojT, *vt;
    cudaGetSymbolAddress((void**)&xh, g_xh);
    cudaGetSymbolAddress((void**)&qkvh, g_qkvh);
    cudaGetSymbolAddress((void**)&ctxh, g_ctxh);
    cudaGetSymbolAddress((void**)&wqkvT, g_wqkvT);
    cudaGetSymbolAddress((void**)&wprojT, g_wprojT);
    cudaGetSymbolAddress((void**)&vt, g_vt);

    const int g_smem = 6 * 10240;     // 61440
    const int a_smem = 144896;        // Qs+Ks+Vs+redO, disjoint
    cudaFuncSetAttribute(gemm_h3,
        cudaFuncAttributeMaxDynamicSharedMemorySize, g_smem);
    cudaFuncSetAttribute(attn_fused_h,
        cudaFuncAttributeMaxDynamicSharedMemorySize, a_smem);

    // 0) One-launch prep: cvt x + both weight transposes
    prep_all<<<8192, 256>>>(x, xh, w_qkv, wqkvT, w_proj, wprojT);

    // 1) QKV projection (fp16 out)
    gemm_h3<<<dim3(3 * CC / 128, BB * NN / 128), 256, g_smem>>>(
        xh, wqkvT, b_qkv, qkvh, BB * NN, 3 * CC, CC, 1);

    // 1b) V transpose -> [bh][d][m]
    transpose_v_h<<<dim3(NN / 128, BB * HH), 256>>>(qkvh, vt);

    // 2) Fully fused attention (V prefetch ring, stores inside PV loop)
    attn_fused_h<<<dim3(NN / FROWS, BB * HH), 512, a_smem>>>(
        qkvh, vt, attn, ctxh);

    // 3) Output projection (fp32 out)
    gemm_h3<<<dim3(CC / 128, BB * NN / 128), 256, g_smem>>>(
        ctxh, wprojT, b_proj, out, BB * NN, CC, CC, 0);
}